// round 1
// baseline (speedup 1.0000x reference)
#include <cuda_runtime.h>
#include <math.h>

// Problem constants: pred/target are [16,1,256,256] fp32.
#define B 16
#define H 256
#define W 256
#define NPIX (B * H * W)   // 1048576

// Scratch (device globals — no allocation allowed).
__device__ float         g_g2T[NPIX];     // g^2, transposed: [B][W][H]
__device__ unsigned char g_predT[NPIX];   // pred edge flag, transposed: [B][W][H]
__device__ double        g_acc;

// ---------------------------------------------------------------------------
// K0: zero accumulator
// ---------------------------------------------------------------------------
__global__ void k_init() { g_acc = 0.0; }

// ---------------------------------------------------------------------------
// K1: per row (b,y): edge maps + 1D row distance (nearest target-edge in row)
// grid = B*H blocks, 256 threads (x = tid)
// ---------------------------------------------------------------------------
__global__ void k_edges(const float* __restrict__ pred,
                        const float* __restrict__ targ) {
    const int row = blockIdx.x;       // 0 .. B*H-1
    const int b = row >> 8;
    const int y = row & 255;
    const int x = threadIdx.x;        // 0 .. 255

    __shared__ unsigned char tb[3][W + 2];   // target bools, halo=true
    __shared__ unsigned char pb[3][W + 2];   // pred bools
    __shared__ unsigned int  tmask[8];       // 256-bit target-edge row mask

    const size_t base = (size_t)b * H * W;

    #pragma unroll
    for (int dy = 0; dy < 3; ++dy) {
        int yy = y + dy - 1;
        bool inb = (yy >= 0) && (yy < H);
        float tv = inb ? targ[base + (size_t)yy * W + x] : 1.0f;
        float pv = inb ? pred[base + (size_t)yy * W + x] : 1.0f;
        tb[dy][x + 1] = (tv > 0.5f) ? 1 : 0;
        pb[dy][x + 1] = (pv > 0.5f) ? 1 : 0;
    }
    if (x == 0) {
        #pragma unroll
        for (int dy = 0; dy < 3; ++dy) {
            tb[dy][0] = 1; tb[dy][W + 1] = 1;   // OOB column == true (never edge-triggering)
            pb[dy][0] = 1; pb[dy][W + 1] = 1;
        }
    }
    __syncthreads();

    // Edge: center true AND some in-bounds 3x3 neighbor false.
    unsigned char tall = tb[0][x] & tb[0][x + 1] & tb[0][x + 2]
                       & tb[1][x]               & tb[1][x + 2]
                       & tb[2][x] & tb[2][x + 1] & tb[2][x + 2];
    bool tedge = tb[1][x + 1] && !tall;

    unsigned char pall = pb[0][x] & pb[0][x + 1] & pb[0][x + 2]
                       & pb[1][x]               & pb[1][x + 2]
                       & pb[2][x] & pb[2][x + 1] & pb[2][x + 2];
    bool pedge = pb[1][x + 1] && !pall;

    unsigned int bal = __ballot_sync(0xFFFFFFFFu, tedge);
    if ((x & 31) == 0) tmask[x >> 5] = bal;

    // pred-edge transposed store [b][x][y]
    g_predT[((size_t)b * W + x) * H + y] = pedge ? 1 : 0;
    __syncthreads();

    // nearest set bit distance in the 256-bit row mask
    int best = 0x7FFFFFFF;
    const int wx = x >> 5, bit = x & 31;
    // left (positions <= x)
    for (int w = wx; w >= 0; --w) {
        unsigned int m = tmask[w];
        if (w == wx) m &= (0xFFFFFFFFu >> (31 - bit));
        if (m) { best = x - (w * 32 + (31 - __clz(m))); break; }
    }
    // right (positions >= x)
    for (int w = wx; w < 8; ++w) {
        unsigned int m = tmask[w];
        if (w == wx) m &= (0xFFFFFFFFu << bit);
        if (m) { int d = (w * 32 + (__ffs(m) - 1)) - x; if (d < best) best = d; break; }
    }

    float g = (best == 0x7FFFFFFF) ? 1e6f : (float)best;
    g_g2T[((size_t)b * W + x) * H + y] = g * g;
}

// ---------------------------------------------------------------------------
// K2: per column (b,x): exact pruned vertical EDT + sum of distances at
// pred-edge pixels. grid = B*W blocks, 256 threads (y = tid)
// ---------------------------------------------------------------------------
__global__ void k_dist() {
    const int col = blockIdx.x;       // b*W + x
    const int y = threadIdx.x;

    __shared__ float         c2[H];
    __shared__ unsigned char pe[H];
    __shared__ double        ws[8];

    const size_t base = (size_t)col * H;
    c2[y] = g_g2T[base + y];
    pe[y] = g_predT[base + y];
    __syncthreads();

    float val = 0.0f;
    if (pe[y]) {
        float d2 = c2[y];
        // exact pruned search: any y' with (y-y')^2 >= d2 cannot improve the min
        for (int r = 1; r < H; ++r) {
            float rr = (float)(r * r);         // exact in fp32 for r <= 255
            if (rr >= d2) break;
            int ym = y - r, yp = y + r;
            if (ym >= 0)  d2 = fminf(d2, rr + c2[ym]);
            if (yp < H)   d2 = fminf(d2, rr + c2[yp]);
        }
        val = sqrtf(d2);
    }

    // block reduction in double
    double v = (double)val;
    #pragma unroll
    for (int o = 16; o; o >>= 1) v += __shfl_down_sync(0xFFFFFFFFu, v, o);
    if ((y & 31) == 0) ws[y >> 5] = v;
    __syncthreads();
    if (y < 8) {
        double t = ws[y];
        #pragma unroll
        for (int o = 4; o; o >>= 1) t += __shfl_down_sync(0x000000FFu, t, o);
        if (y == 0) atomicAdd(&g_acc, t);
    }
}

// ---------------------------------------------------------------------------
// K3: finalize mean
// ---------------------------------------------------------------------------
__global__ void k_final(float* __restrict__ out) {
    out[0] = (float)(g_acc * (1.0 / (double)NPIX));
}

extern "C" void kernel_launch(void* const* d_in, const int* in_sizes, int n_in,
                              void* d_out, int out_size) {
    const float* pred = (const float*)d_in[0];
    const float* targ = (const float*)d_in[1];
    float* out = (float*)d_out;

    k_init<<<1, 1>>>();
    k_edges<<<B * H, W>>>(pred, targ);
    k_dist<<<B * W, H>>>();
    k_final<<<1, 1>>>(out);
}

// round 3
// speedup vs baseline: 1.3694x; 1.3694x over previous
#include <cuda_runtime.h>
#include <math.h>

// Problem constants: pred/target are [16,1,256,256] fp32.
#define B 16
#define H 256
#define W 256
#define NPIX (B * H * W)   // 1048576
#define NPART 64

// Scratch (device globals — no allocation allowed).
__device__ float         g_g2T[NPIX];     // g^2, transposed: [B][W][H]
__device__ unsigned char g_predT[NPIX];   // pred edge flag, transposed: [B][W][H]
__device__ double        g_part[NPART];   // partial sums
__device__ unsigned int  g_done;          // completion ticket for k_dist

// ---------------------------------------------------------------------------
// K1: per row (b,y): edge maps + 1D row distance (nearest target-edge in row).
// Also zeroes the reduction state (block 0) for the k_dist pass that follows.
// grid = B*H blocks, 256 threads (x = tid)
// ---------------------------------------------------------------------------
__global__ void k_edges(const float* __restrict__ pred,
                        const float* __restrict__ targ) {
    const int row = blockIdx.x;       // 0 .. B*H-1
    const int b = row >> 8;
    const int y = row & 255;
    const int x = threadIdx.x;        // 0 .. 255

    if (blockIdx.x == 0) {
        if (x < NPART) g_part[x] = 0.0;
        if (x == 0)    g_done = 0u;
    }

    __shared__ unsigned char tb[3][W + 2];   // target bools, halo=true
    __shared__ unsigned char pb[3][W + 2];   // pred bools
    __shared__ unsigned int  tmask[8];       // 256-bit target-edge row mask

    const size_t base = (size_t)b * H * W;

    #pragma unroll
    for (int dy = 0; dy < 3; ++dy) {
        int yy = y + dy - 1;
        bool inb = (yy >= 0) && (yy < H);
        float tv = inb ? targ[base + (size_t)yy * W + x] : 1.0f;
        float pv = inb ? pred[base + (size_t)yy * W + x] : 1.0f;
        tb[dy][x + 1] = (tv > 0.5f) ? 1 : 0;
        pb[dy][x + 1] = (pv > 0.5f) ? 1 : 0;
    }
    if (x == 0) {
        #pragma unroll
        for (int dy = 0; dy < 3; ++dy) {
            tb[dy][0] = 1; tb[dy][W + 1] = 1;   // OOB column == true (never edge-triggering)
            pb[dy][0] = 1; pb[dy][W + 1] = 1;
        }
    }
    __syncthreads();

    // Edge: center true AND some in-bounds 3x3 neighbor false.
    unsigned char tall = tb[0][x] & tb[0][x + 1] & tb[0][x + 2]
                       & tb[1][x]               & tb[1][x + 2]
                       & tb[2][x] & tb[2][x + 1] & tb[2][x + 2];
    bool tedge = tb[1][x + 1] && !tall;

    unsigned char pall = pb[0][x] & pb[0][x + 1] & pb[0][x + 2]
                       & pb[1][x]               & pb[1][x + 2]
                       & pb[2][x] & pb[2][x + 1] & pb[2][x + 2];
    bool pedge = pb[1][x + 1] && !pall;

    unsigned int bal = __ballot_sync(0xFFFFFFFFu, tedge);
    if ((x & 31) == 0) tmask[x >> 5] = bal;

    // pred-edge transposed store [b][x][y]
    g_predT[((size_t)b * W + x) * H + y] = pedge ? 1 : 0;
    __syncthreads();

    // nearest set bit distance in the 256-bit row mask
    int best = 0x7FFFFFFF;
    const int wx = x >> 5, bit = x & 31;
    // left (positions <= x)
    for (int w = wx; w >= 0; --w) {
        unsigned int m = tmask[w];
        if (w == wx) m &= (0xFFFFFFFFu >> (31 - bit));
        if (m) { best = x - (w * 32 + (31 - __clz(m))); break; }
    }
    // right (positions >= x)
    for (int w = wx; w < 8; ++w) {
        unsigned int m = tmask[w];
        if (w == wx) m &= (0xFFFFFFFFu << bit);
        if (m) { int d = (w * 32 + (__ffs(m) - 1)) - x; if (d < best) best = d; break; }
    }

    float g = (best == 0x7FFFFFFF) ? 1e6f : (float)best;
    g_g2T[((size_t)b * W + x) * H + y] = g * g;
}

// ---------------------------------------------------------------------------
// K2: per column (b,x): exact pruned vertical EDT + sum of distances at
// pred-edge pixels. Last block to finish sums the partials and writes the
// mean. grid = B*W blocks, 256 threads (y = tid)
// ---------------------------------------------------------------------------
__global__ void k_dist(float* __restrict__ out) {
    const int col = blockIdx.x;       // b*W + x
    const int y = threadIdx.x;

    __shared__ float         c2[H];
    __shared__ unsigned char pe[H];
    __shared__ double        ws[8];
    __shared__ bool          amlast;

    const size_t base = (size_t)col * H;
    c2[y] = g_g2T[base + y];
    pe[y] = g_predT[base + y];
    __syncthreads();

    float val = 0.0f;
    if (pe[y]) {
        float d2 = c2[y];
        // exact pruned search: any y' with (y-y')^2 >= d2 cannot improve the min
        for (int r = 1; r < H; ++r) {
            float rr = (float)(r * r);         // exact in fp32 for r <= 255
            if (rr >= d2) break;
            int ym = y - r, yp = y + r;
            if (ym >= 0)  d2 = fminf(d2, rr + c2[ym]);
            if (yp < H)   d2 = fminf(d2, rr + c2[yp]);
        }
        val = sqrtf(d2);
    }

    // block reduction in double
    double v = (double)val;
    #pragma unroll
    for (int o = 16; o; o >>= 1) v += __shfl_down_sync(0xFFFFFFFFu, v, o);
    if ((y & 31) == 0) ws[y >> 5] = v;
    __syncthreads();
    if (y == 0) {
        double t = ws[0] + ws[1] + ws[2] + ws[3] + ws[4] + ws[5] + ws[6] + ws[7];
        atomicAdd(&g_part[col & (NPART - 1)], t);
        __threadfence();
        unsigned int ticket = atomicAdd(&g_done, 1u);
        amlast = (ticket == (unsigned int)(gridDim.x - 1));
    }
    __syncthreads();

    // last block finalizes the mean
    if (amlast && y == 0) {
        double s = 0.0;
        #pragma unroll
        for (int i = 0; i < NPART; ++i) s += g_part[i];
        out[0] = (float)(s * (1.0 / (double)NPIX));
    }
}

extern "C" void kernel_launch(void* const* d_in, const int* in_sizes, int n_in,
                              void* d_out, int out_size) {
    const float* pred = (const float*)d_in[0];
    const float* targ = (const float*)d_in[1];
    float* out = (float*)d_out;

    k_edges<<<B * H, W>>>(pred, targ);
    k_dist<<<B * W, H>>>(out);
}

// round 4
// speedup vs baseline: 2.0370x; 1.4875x over previous
#include <cuda_runtime.h>
#include <math.h>

// Problem constants: pred/target are [16,1,256,256] fp32.
#define B 16
#define H 256
#define W 256
#define NPIX (B * H * W)   // 1048576
#define NBLK 128           // 16 batches x 8 row-tiles of 32

// Scratch (device globals — no allocation allowed; zero-init at load).
// g2 transposed [B][W][H], stored as uint: bits 0..30 = fp32 g^2 (g^2 >= 0),
// bit 31 = pred-edge flag.
__device__ unsigned int g_g2T[NPIX];
__device__ float        g_part[NBLK];
__device__ unsigned int g_bar;     // monotonic grid-barrier counter

// ---------------------------------------------------------------------------
// Grid barrier: monotonic counter, release/acquire via threadfence.
// Safe: all NBLK blocks are co-resident (NBLK <= #SMs, 1 block/SM fits).
// ---------------------------------------------------------------------------
__device__ __forceinline__ void grid_barrier() {
    __syncthreads();
    if (threadIdx.x == 0) {
        __threadfence();
        unsigned int t = atomicAdd(&g_bar, 1u);
        unsigned int target = ((t >> 7) + 1u) << 7;   // next multiple of 128
        while (*(volatile unsigned int*)&g_bar < target) { }
        __threadfence();
    }
    __syncthreads();
}

// Nearest set-bit distance in a 256-bit mask (8 words), position x.
__device__ __forceinline__ int nearest_dist(const unsigned int* __restrict__ mask, int x) {
    int best = 0x7FFFFFFF;
    const int wx = x >> 5, bit = x & 31;
    unsigned int m = mask[wx] & (0xFFFFFFFFu >> (31 - bit));   // bits <= x
    if (m) {
        best = bit - (31 - __clz(m));
    } else {
        for (int w = wx - 1; w >= 0; --w) {
            unsigned int mm = mask[w];
            if (mm) { best = x - (w * 32 + 31 - __clz(mm)); break; }
        }
    }
    unsigned int m2 = mask[wx] & (0xFFFFFFFFu << bit);         // bits >= x
    if (m2) {
        int d = (__ffs(m2) - 1) - bit;
        if (d < best) best = d;
    } else {
        for (int w = wx + 1; w < 8; ++w) {
            unsigned int mm = mask[w];
            if (mm) { int d = w * 32 + (__ffs(mm) - 1) - x; if (d < best) best = d; break; }
        }
    }
    return best;
}

// ---------------------------------------------------------------------------
// Single fused kernel. grid = 128 blocks x 256 threads.
// Phase A: per 32-row tile: edges (bitwise), 1D row distance, transpose-store.
// Phase B: per 32 columns: exact pruned vertical EDT + masked distance sum.
// ---------------------------------------------------------------------------
__global__ void __launch_bounds__(256) edge_loss_fused(
        const float* __restrict__ pred,
        const float* __restrict__ targ,
        float* __restrict__ out) {
    const int bid  = blockIdx.x;          // 0..127
    const int tid  = threadIdx.x;         // 0..255
    const int lane = tid & 31;
    const int wid  = tid >> 5;

    __shared__ unsigned int mt[34][8], mp[34][8];       // raw bool masks (halo rows)
    __shared__ unsigned int ht[34][8], hp[34][8];       // horizontal 3-AND
    __shared__ unsigned int te[32][8], pemask[32][8];   // edge masks
    __shared__ unsigned int sg2[32][257];               // g2+flag tile (padded)
    __shared__ float        craw_f[4][257];             // phase B columns (as uint bits)
    __shared__ float        wsum[8];

    // ===================== Phase A: rows =====================
    {
        const int b  = bid >> 3;
        const int y0 = (bid & 7) * 32;
        const int ibase = b * (H * W);

        // Build bool bitmasks for rows y0-1 .. y0+32 (OOB row == all-true).
        for (int r = 0; r < 34; ++r) {
            int yy = y0 + r - 1;
            bool inb = (yy >= 0) && (yy < H);
            int off = ibase + yy * W + tid;
            float tv = inb ? targ[off] : 1.0f;
            float pv = inb ? pred[off] : 1.0f;
            unsigned int mtb = __ballot_sync(0xFFFFFFFFu, tv > 0.5f);
            unsigned int mpb = __ballot_sync(0xFFFFFFFFu, pv > 0.5f);
            if (lane == 0) { mt[r][wid] = mtb; mp[r][wid] = mpb; }
        }
        __syncthreads();

        // Horizontal 3-AND with cross-word carry (OOB column == true).
        for (int i = tid; i < 34 * 8; i += 256) {
            int r = i >> 3, w = i & 7;
            unsigned int m, lo, hi;
            m  = mt[r][w];
            lo = (w > 0) ? (mt[r][w - 1] >> 31) : 1u;
            hi = (w < 7) ? (mt[r][w + 1] & 1u)  : 1u;
            ht[r][w] = m & ((m << 1) | lo) & ((m >> 1) | (hi << 31));
            m  = mp[r][w];
            lo = (w > 0) ? (mp[r][w - 1] >> 31) : 1u;
            hi = (w < 7) ? (mp[r][w + 1] & 1u)  : 1u;
            hp[r][w] = m & ((m << 1) | lo) & ((m >> 1) | (hi << 31));
        }
        __syncthreads();

        // Edge = center & ~(AND of 3x3 neighborhood).
        for (int i = tid; i < 32 * 8; i += 256) {
            int r = i >> 3, w = i & 7;
            unsigned int a9t = ht[r][w] & ht[r + 1][w] & ht[r + 2][w];
            te[r][w] = mt[r + 1][w] & ~a9t;
            unsigned int a9p = hp[r][w] & hp[r + 1][w] & hp[r + 2][w];
            pemask[r][w] = mp[r + 1][w] & ~a9p;
        }
        __syncthreads();

        // Per-pixel 1D row distance; pack g^2 (fp32) + pred-edge flag (bit31).
        for (int r = 0; r < 32; ++r) {
            int best = nearest_dist(te[r], tid);
            float g = (best == 0x7FFFFFFF) ? 1e6f : (float)best;
            unsigned int peb = (pemask[r][tid >> 5] >> (tid & 31)) & 1u;
            sg2[r][tid] = __float_as_uint(g * g) | (peb << 31);
        }
        __syncthreads();

        // Transpose store: warp writes 32 consecutive y for one x -> 128B lines.
        for (int p = 0; p < 32; ++p) {
            int x = p * 8 + wid;
            g_g2T[(b * W + x) * H + y0 + lane] = sg2[lane][x];
        }
    }

    grid_barrier();

    // ===================== Phase B: columns =====================
    unsigned int (*craw)[257] = (unsigned int (*)[257])craw_f;
    float acc = 0.0f;
    for (int grp = 0; grp < 8; ++grp) {
        __syncthreads();   // protect smem reuse across groups
        const int colbase = bid * 32 + grp * 4;
        for (int k = 0; k < 4; ++k) {
            int idx = tid + k * 256;          // 0..1023
            int c = idx >> 8, y = idx & 255;
            craw[c][y] = g_g2T[(size_t)(colbase + c) * H + y];
        }
        __syncthreads();
        #pragma unroll
        for (int c = 0; c < 4; ++c) {
            unsigned int raw = craw[c][tid];
            if (raw >> 31) {                   // pred-edge pixel
                float d2 = __uint_as_float(raw & 0x7FFFFFFFu);
                for (int r = 1; r < H; ++r) {
                    float rr = (float)(r * r); // exact in fp32 for r <= 255
                    if (rr >= d2) break;
                    int ym = tid - r, yp = tid + r;
                    if (ym >= 0) d2 = fminf(d2, rr + __uint_as_float(craw[c][ym] & 0x7FFFFFFFu));
                    if (yp < H)  d2 = fminf(d2, rr + __uint_as_float(craw[c][yp] & 0x7FFFFFFFu));
                }
                acc += sqrtf(d2);
            }
        }
    }

    // Block reduction (fp32, fixed order -> deterministic).
    #pragma unroll
    for (int o = 16; o; o >>= 1) acc += __shfl_down_sync(0xFFFFFFFFu, acc, o);
    if (lane == 0) wsum[wid] = acc;
    __syncthreads();
    if (tid == 0) {
        float s = wsum[0] + wsum[1] + wsum[2] + wsum[3]
                + wsum[4] + wsum[5] + wsum[6] + wsum[7];
        g_part[bid] = s;
    }

    grid_barrier();

    // Block 0 finalizes (fixed-order tree -> deterministic).
    if (bid == 0) {
        float v = (tid < NBLK) ? g_part[tid] : 0.0f;
        #pragma unroll
        for (int o = 16; o; o >>= 1) v += __shfl_down_sync(0xFFFFFFFFu, v, o);
        if (lane == 0) wsum[wid] = v;
        __syncthreads();
        if (tid == 0) {
            double s = (double)wsum[0] + wsum[1] + wsum[2] + wsum[3];
            out[0] = (float)(s / (double)NPIX);
        }
    }
}

extern "C" void kernel_launch(void* const* d_in, const int* in_sizes, int n_in,
                              void* d_out, int out_size) {
    const float* pred = (const float*)d_in[0];
    const float* targ = (const float*)d_in[1];
    float* out = (float*)d_out;

    edge_loss_fused<<<NBLK, 256>>>(pred, targ, out);
}

// round 5
// speedup vs baseline: 3.1622x; 1.5524x over previous
#include <cuda_runtime.h>
#include <math.h>

// Problem constants: pred/target are [16,1,256,256] fp32.
#define B 16
#define H 256
#define W 256
#define NPIX (B * H * W)   // 1048576
#define NBLK 256           // 16 batches x 16 row-tiles of 16 rows
#define TROWS 16           // rows per phase-A tile
#define TCOLS 16           // columns per phase-B block

// Scratch (device globals — no allocation allowed; zero-init at load).
// g2 transposed [B][W][H] as uint: bits 0..30 = fp32 g^2, bit 31 = pred-edge.
__device__ unsigned int g_g2T[NPIX];
__device__ float        g_part[NBLK];
__device__ unsigned int g_bar;     // monotonic grid-barrier counter

// ---------------------------------------------------------------------------
// Grid barrier: monotonic counter. Safe: all NBLK blocks co-resident
// (occupancy limit >= 2 blocks/SM, 256 <= 148*2).
// ---------------------------------------------------------------------------
__device__ __forceinline__ void grid_barrier() {
    __syncthreads();
    if (threadIdx.x == 0) {
        __threadfence();
        unsigned int t = atomicAdd(&g_bar, 1u);
        unsigned int target = (t / NBLK + 1u) * NBLK;
        while (*(volatile unsigned int*)&g_bar < target) { __nanosleep(64); }
        __threadfence();
    }
    __syncthreads();
}

// Nearest set-bit distance in a 256-bit mask (8 words), position x.
__device__ __forceinline__ int nearest_dist(const unsigned int* __restrict__ mask, int x) {
    int best = 0x7FFFFFFF;
    const int wx = x >> 5, bit = x & 31;
    unsigned int m = mask[wx] & (0xFFFFFFFFu >> (31 - bit));   // bits <= x
    if (m) {
        best = bit - (31 - __clz(m));
    } else {
        for (int w = wx - 1; w >= 0; --w) {
            unsigned int mm = mask[w];
            if (mm) { best = x - (w * 32 + 31 - __clz(mm)); break; }
        }
    }
    unsigned int m2 = mask[wx] & (0xFFFFFFFFu << bit);         // bits >= x
    if (m2) {
        int d = (__ffs(m2) - 1) - bit;
        if (d < best) best = d;
    } else {
        for (int w = wx + 1; w < 8; ++w) {
            unsigned int mm = mask[w];
            if (mm) { int d = w * 32 + (__ffs(mm) - 1) - x; if (d < best) best = d; break; }
        }
    }
    return best;
}

// ---------------------------------------------------------------------------
// Single fused kernel. grid = 256 blocks x 256 threads.
// Phase A: 16-row tile: edges (bitwise), 1D row distance, transpose-store.
// Phase B: 16 columns: exact pruned vertical EDT + masked distance sum.
// ---------------------------------------------------------------------------
__global__ void __launch_bounds__(256) edge_loss_fused(
        const float* __restrict__ pred,
        const float* __restrict__ targ,
        float* __restrict__ out) {
    const int bid  = blockIdx.x;          // 0..255
    const int tid  = threadIdx.x;         // 0..255
    const int lane = tid & 31;
    const int wid  = tid >> 5;

    __shared__ unsigned int mt[TROWS + 2][8], mp[TROWS + 2][8];   // bool masks (+halo)
    __shared__ unsigned int ht[TROWS + 2][8], hp[TROWS + 2][8];   // horizontal 3-AND
    __shared__ unsigned int te[TROWS][8], pemask[TROWS][8];       // edge masks
    __shared__ unsigned int sg2[TROWS][258];                       // g2+flag (pad 258)
    __shared__ float        craw_f[4][257];                        // phase-B columns
    __shared__ float        wsum[8];

    // ===================== Phase A: rows =====================
    {
        const int b  = bid >> 4;
        const int y0 = (bid & 15) * TROWS;
        const int ibase = b * (H * W);

        // Bool bitmasks for rows y0-1 .. y0+16 (OOB row == all-true).
        for (int r = 0; r < TROWS + 2; ++r) {
            int yy = y0 + r - 1;
            bool inb = (yy >= 0) && (yy < H);
            int off = ibase + yy * W + tid;
            float tv = inb ? targ[off] : 1.0f;
            float pv = inb ? pred[off] : 1.0f;
            unsigned int mtb = __ballot_sync(0xFFFFFFFFu, tv > 0.5f);
            unsigned int mpb = __ballot_sync(0xFFFFFFFFu, pv > 0.5f);
            if (lane == 0) { mt[r][wid] = mtb; mp[r][wid] = mpb; }
        }
        __syncthreads();

        // Horizontal 3-AND with cross-word carry (OOB column == true).
        if (tid < (TROWS + 2) * 8) {
            int r = tid >> 3, w = tid & 7;
            unsigned int m, lo, hi;
            m  = mt[r][w];
            lo = (w > 0) ? (mt[r][w - 1] >> 31) : 1u;
            hi = (w < 7) ? (mt[r][w + 1] & 1u)  : 1u;
            ht[r][w] = m & ((m << 1) | lo) & ((m >> 1) | (hi << 31));
            m  = mp[r][w];
            lo = (w > 0) ? (mp[r][w - 1] >> 31) : 1u;
            hi = (w < 7) ? (mp[r][w + 1] & 1u)  : 1u;
            hp[r][w] = m & ((m << 1) | lo) & ((m >> 1) | (hi << 31));
        }
        __syncthreads();

        // Edge = center & ~(AND of 3x3 neighborhood).
        if (tid < TROWS * 8) {
            int r = tid >> 3, w = tid & 7;
            unsigned int a9t = ht[r][w] & ht[r + 1][w] & ht[r + 2][w];
            te[r][w] = mt[r + 1][w] & ~a9t;
            unsigned int a9p = hp[r][w] & hp[r + 1][w] & hp[r + 2][w];
            pemask[r][w] = mp[r + 1][w] & ~a9p;
        }
        __syncthreads();

        // Per-pixel 1D row distance; pack g^2 (fp32) + pred-edge flag (bit31).
        #pragma unroll 4
        for (int r = 0; r < TROWS; ++r) {
            int best = nearest_dist(te[r], tid);
            float g = (best == 0x7FFFFFFF) ? 1e6f : (float)best;
            unsigned int peb = (pemask[r][tid >> 5] >> (tid & 31)) & 1u;
            sg2[r][tid] = __float_as_uint(g * g) | (peb << 31);
        }
        __syncthreads();

        // Transpose store: thread t handles (y = t&15, xi = t>>4); 16 iters.
        const int ty = tid & 15, txi = tid >> 4;
        #pragma unroll 4
        for (int p = 0; p < 16; ++p) {
            int x = p * 16 + txi;
            g_g2T[(b * W + x) * H + y0 + ty] = sg2[ty][x];
        }
    }

    grid_barrier();

    // ===================== Phase B: columns =====================
    unsigned int (*craw)[257] = (unsigned int (*)[257])craw_f;
    float acc = 0.0f;
    #pragma unroll
    for (int grp = 0; grp < TCOLS / 4; ++grp) {
        __syncthreads();   // protect smem reuse across groups
        const int colbase = bid * TCOLS + grp * 4;
        #pragma unroll
        for (int k = 0; k < 4; ++k) {
            int idx = tid + k * 256;          // 0..1023
            int c = idx >> 8, y = idx & 255;
            craw[c][y] = g_g2T[(size_t)(colbase + c) * H + y];
        }
        __syncthreads();
        #pragma unroll
        for (int c = 0; c < 4; ++c) {
            unsigned int raw = craw[c][tid];
            if (raw >> 31) {                   // pred-edge pixel
                float d2 = __uint_as_float(raw & 0x7FFFFFFFu);
                for (int r = 1; r < H; ++r) {
                    float rr = (float)(r * r); // exact in fp32 for r <= 255
                    if (rr >= d2) break;
                    int ym = tid - r, yp = tid + r;
                    if (ym >= 0) d2 = fminf(d2, rr + __uint_as_float(craw[c][ym] & 0x7FFFFFFFu));
                    if (yp < H)  d2 = fminf(d2, rr + __uint_as_float(craw[c][yp] & 0x7FFFFFFFu));
                }
                acc += sqrtf(d2);
            }
        }
    }

    // Block reduction (fp32, fixed order -> deterministic).
    #pragma unroll
    for (int o = 16; o; o >>= 1) acc += __shfl_down_sync(0xFFFFFFFFu, acc, o);
    if (lane == 0) wsum[wid] = acc;
    __syncthreads();
    if (tid == 0) {
        float s = wsum[0] + wsum[1] + wsum[2] + wsum[3]
                + wsum[4] + wsum[5] + wsum[6] + wsum[7];
        g_part[bid] = s;
    }

    grid_barrier();

    // Block 0 finalizes (fixed-order tree -> deterministic).
    if (bid == 0) {
        float v = g_part[tid];
        #pragma unroll
        for (int o = 16; o; o >>= 1) v += __shfl_down_sync(0xFFFFFFFFu, v, o);
        if (lane == 0) wsum[wid] = v;
        __syncthreads();
        if (tid == 0) {
            double s = 0.0;
            #pragma unroll
            for (int i = 0; i < 8; ++i) s += (double)wsum[i];
            out[0] = (float)(s / (double)NPIX);
        }
    }
}

extern "C" void kernel_launch(void* const* d_in, const int* in_sizes, int n_in,
                              void* d_out, int out_size) {
    const float* pred = (const float*)d_in[0];
    const float* targ = (const float*)d_in[1];
    float* out = (float*)d_out;

    edge_loss_fused<<<NBLK, 256>>>(pred, targ, out);
}

// round 6
// speedup vs baseline: 3.5522x; 1.1233x over previous
#include <cuda_runtime.h>
#include <math.h>

// Problem constants: pred/target are [16,1,256,256] fp32.
#define B 16
#define H 256
#define W 256
#define NPIX (B * H * W)   // 1048576
#define NBLK 512           // 16 batches x 32 row-tiles of 8 rows
#define TROWS 8            // rows per phase-A tile
#define TCOLS 8            // columns per phase-B block

// Scratch (device globals — no allocation allowed; zero-init at load).
// g2 transposed [B][W][H] as uint: bits 0..30 = fp32 g^2, bit 31 = pred-edge.
__device__ unsigned int g_g2T[NPIX];
__device__ float        g_part[NBLK];
__device__ unsigned int g_bar;     // monotonic grid-barrier counter
__device__ unsigned int g_tick;    // monotonic completion ticket

// ---------------------------------------------------------------------------
// Grid barrier: monotonic counter. Safe: all NBLK blocks co-resident
// (4 blocks/SM by smem/regs; 512 <= 148*4).
// ---------------------------------------------------------------------------
__device__ __forceinline__ void grid_barrier() {
    __syncthreads();
    if (threadIdx.x == 0) {
        __threadfence();
        unsigned int t = atomicAdd(&g_bar, 1u);
        unsigned int target = (t / NBLK + 1u) * NBLK;
        while (*(volatile unsigned int*)&g_bar < target) { __nanosleep(64); }
        __threadfence();
    }
    __syncthreads();
}

// Nearest set-bit distance in a 256-bit mask (8 words), position x.
__device__ __forceinline__ int nearest_dist(const unsigned int* __restrict__ mask, int x) {
    int best = 0x7FFFFFFF;
    const int wx = x >> 5, bit = x & 31;
    unsigned int m = mask[wx] & (0xFFFFFFFFu >> (31 - bit));   // bits <= x
    if (m) {
        best = bit - (31 - __clz(m));
    } else {
        for (int w = wx - 1; w >= 0; --w) {
            unsigned int mm = mask[w];
            if (mm) { best = x - (w * 32 + 31 - __clz(mm)); break; }
        }
    }
    unsigned int m2 = mask[wx] & (0xFFFFFFFFu << bit);         // bits >= x
    if (m2) {
        int d = (__ffs(m2) - 1) - bit;
        if (d < best) best = d;
    } else {
        for (int w = wx + 1; w < 8; ++w) {
            unsigned int mm = mask[w];
            if (mm) { int d = w * 32 + (__ffs(mm) - 1) - x; if (d < best) best = d; break; }
        }
    }
    return best;
}

// ---------------------------------------------------------------------------
// Single fused kernel. grid = 512 blocks x 256 threads.
// Phase A: 8-row tile: edges (bitwise), 1D row distance, transpose-store.
// Phase B: 8 columns: exact pruned vertical EDT + masked distance sum.
// Finalize: last-finished block reduces the 512 partials (fixed order).
// ---------------------------------------------------------------------------
__global__ void __launch_bounds__(256, 4) edge_loss_fused(
        const float* __restrict__ pred,
        const float* __restrict__ targ,
        float* __restrict__ out) {
    const int bid  = blockIdx.x;          // 0..511
    const int tid  = threadIdx.x;         // 0..255
    const int lane = tid & 31;
    const int wid  = tid >> 5;

    __shared__ unsigned int mt[TROWS + 2][8], mp[TROWS + 2][8];   // bool masks (+halo)
    __shared__ unsigned int ht[TROWS + 2][8], hp[TROWS + 2][8];   // horizontal 3-AND
    __shared__ unsigned int te[TROWS][8], pemask[TROWS][8];       // edge masks
    __shared__ unsigned int sg2[TROWS][258];                       // g2+flag (padded)
    __shared__ float        craw_f[4][257];                        // phase-B columns
    __shared__ float        wsum[8];
    __shared__ bool         amlast;

    // ===================== Phase A: rows =====================
    {
        const int b  = bid >> 5;
        const int y0 = (bid & 31) * TROWS;
        const int ibase = b * (H * W);

        // Bool bitmasks for rows y0-1 .. y0+8 (OOB row == all-true).
        #pragma unroll
        for (int r = 0; r < TROWS + 2; ++r) {
            int yy = y0 + r - 1;
            bool inb = (yy >= 0) && (yy < H);
            int off = ibase + yy * W + tid;
            float tv = inb ? targ[off] : 1.0f;
            float pv = inb ? pred[off] : 1.0f;
            unsigned int mtb = __ballot_sync(0xFFFFFFFFu, tv > 0.5f);
            unsigned int mpb = __ballot_sync(0xFFFFFFFFu, pv > 0.5f);
            if (lane == 0) { mt[r][wid] = mtb; mp[r][wid] = mpb; }
        }
        __syncthreads();

        // Horizontal 3-AND with cross-word carry (OOB column == true).
        if (tid < (TROWS + 2) * 8) {
            int r = tid >> 3, w = tid & 7;
            unsigned int m, lo, hi;
            m  = mt[r][w];
            lo = (w > 0) ? (mt[r][w - 1] >> 31) : 1u;
            hi = (w < 7) ? (mt[r][w + 1] & 1u)  : 1u;
            ht[r][w] = m & ((m << 1) | lo) & ((m >> 1) | (hi << 31));
            m  = mp[r][w];
            lo = (w > 0) ? (mp[r][w - 1] >> 31) : 1u;
            hi = (w < 7) ? (mp[r][w + 1] & 1u)  : 1u;
            hp[r][w] = m & ((m << 1) | lo) & ((m >> 1) | (hi << 31));
        }
        __syncthreads();

        // Edge = center & ~(AND of 3x3 neighborhood).
        if (tid < TROWS * 8) {
            int r = tid >> 3, w = tid & 7;
            unsigned int a9t = ht[r][w] & ht[r + 1][w] & ht[r + 2][w];
            te[r][w] = mt[r + 1][w] & ~a9t;
            unsigned int a9p = hp[r][w] & hp[r + 1][w] & hp[r + 2][w];
            pemask[r][w] = mp[r + 1][w] & ~a9p;
        }
        __syncthreads();

        // Per-pixel 1D row distance; pack g^2 (fp32) + pred-edge flag (bit31).
        #pragma unroll
        for (int r = 0; r < TROWS; ++r) {
            int best = nearest_dist(te[r], tid);
            float g = (best == 0x7FFFFFFF) ? 1e6f : (float)best;
            unsigned int peb = (pemask[r][tid >> 5] >> (tid & 31)) & 1u;
            sg2[r][tid] = __float_as_uint(g * g) | (peb << 31);
        }
        __syncthreads();

        // Transpose store: thread t -> (y = t&7, xi = t>>3); 8 iterations.
        const int ty = tid & 7, txi = tid >> 3;
        #pragma unroll
        for (int p = 0; p < 8; ++p) {
            int x = p * 32 + txi;
            g_g2T[(b * W + x) * H + y0 + ty] = sg2[ty][x];
        }
    }

    grid_barrier();

    // ===================== Phase B: columns =====================
    unsigned int (*craw)[257] = (unsigned int (*)[257])craw_f;
    float acc = 0.0f;
    #pragma unroll
    for (int grp = 0; grp < TCOLS / 4; ++grp) {
        __syncthreads();   // protect smem reuse across groups
        const int colbase = bid * TCOLS + grp * 4;
        #pragma unroll
        for (int k = 0; k < 4; ++k) {
            int idx = tid + k * 256;          // 0..1023
            int c = idx >> 8, y = idx & 255;
            craw[c][y] = g_g2T[(size_t)(colbase + c) * H + y];
        }
        __syncthreads();
        #pragma unroll
        for (int c = 0; c < 4; ++c) {
            unsigned int raw = craw[c][tid];
            if (raw >> 31) {                   // pred-edge pixel
                float d2 = __uint_as_float(raw & 0x7FFFFFFFu);
                for (int r = 1; r < H; ++r) {
                    float rr = (float)(r * r); // exact in fp32 for r <= 255
                    if (rr >= d2) break;
                    int ym = tid - r, yp = tid + r;
                    if (ym >= 0) d2 = fminf(d2, rr + __uint_as_float(craw[c][ym] & 0x7FFFFFFFu));
                    if (yp < H)  d2 = fminf(d2, rr + __uint_as_float(craw[c][yp] & 0x7FFFFFFFu));
                }
                acc += sqrtf(d2);
            }
        }
    }

    // Block reduction (fp32, fixed order -> deterministic).
    #pragma unroll
    for (int o = 16; o; o >>= 1) acc += __shfl_down_sync(0xFFFFFFFFu, acc, o);
    if (lane == 0) wsum[wid] = acc;
    __syncthreads();
    if (tid == 0) {
        float s = wsum[0] + wsum[1] + wsum[2] + wsum[3]
                + wsum[4] + wsum[5] + wsum[6] + wsum[7];
        g_part[bid] = s;
        __threadfence();
        unsigned int t = atomicAdd(&g_tick, 1u);   // monotonic across graph replays
        amlast = ((t % NBLK) == (NBLK - 1));
    }
    __syncthreads();

    // Last-finished block reduces all partials (fixed order -> deterministic).
    if (amlast) {
        float v = g_part[tid] + g_part[tid + 256];
        #pragma unroll
        for (int o = 16; o; o >>= 1) v += __shfl_down_sync(0xFFFFFFFFu, v, o);
        if (lane == 0) wsum[wid] = v;
        __syncthreads();
        if (tid == 0) {
            double s = 0.0;
            #pragma unroll
            for (int i = 0; i < 8; ++i) s += (double)wsum[i];
            out[0] = (float)(s / (double)NPIX);
        }
    }
}

extern "C" void kernel_launch(void* const* d_in, const int* in_sizes, int n_in,
                              void* d_out, int out_size) {
    const float* pred = (const float*)d_in[0];
    const float* targ = (const float*)d_in[1];
    float* out = (float*)d_out;

    edge_loss_fused<<<NBLK, 256>>>(pred, targ, out);
}